// round 12
// baseline (speedup 1.0000x reference)
#include <cuda_runtime.h>
#include <cuda_bf16.h>
#include <math.h>

#define NN 50000
#define NE 600000

typedef unsigned int u32;

// Scratch (allocation-free: static __device__ globals)
__device__ float g_X [NN * 128];   // [n][m(0..3)][c]
__device__ float g_M0[NN * 64];    // [n][s(0:p0,1:p3)][c]
__device__ float g_M1[NN * 288];   // [n][p(0:p1,1:p2,2:p4)][m(0..2)][c]

__device__ __forceinline__ float act(float x) {
    return 1.6765324703310907f * x * (1.0f / (1.0f + __expf(-x)));
}

// split-pack a pair (v0 -> low half, v1 -> high half): {hi bf16x2, residual bf16x2}
__device__ __forceinline__ uint2 bsplit2(float v0, float v1) {
    u32 h;
    asm("cvt.rn.bf16x2.f32 %0, %1, %2;" : "=r"(h) : "f"(v1), "f"(v0));
    float h0 = __uint_as_float(h << 16);
    float h1 = __uint_as_float(h & 0xFFFF0000u);
    float r0 = v0 - h0, r1 = v1 - h1;
    u32 l;
    asm("cvt.rn.bf16x2.f32 %0, %1, %2;" : "=r"(l) : "f"(r1), "f"(r0));
    return make_uint2(h, l);
}

__device__ __forceinline__ void mma16816(float* d, u32 a0, u32 a1, u32 a2, u32 a3,
                                         u32 b0, u32 b1) {
    asm("mma.sync.aligned.m16n8k16.row.col.f32.bf16.bf16.f32 "
        "{%0,%1,%2,%3}, {%4,%5,%6,%7}, {%8,%9}, {%0,%1,%2,%3};"
        : "+f"(d[0]), "+f"(d[1]), "+f"(d[2]), "+f"(d[3])
        : "r"(a0), "r"(a1), "r"(a2), "r"(a3), "r"(b0), "r"(b1));
}

#define STR 36   // staging row stride (u32): bank = (4g+tq)%32, conflict-free

// ---------------------------------------------------------------------------
// K1: per-node skip + first linear. 2 nodes per warp iteration. (unchanged)
// ---------------------------------------------------------------------------
__global__ void __launch_bounds__(512) k_node(
    const float* __restrict__ na,     // (N, 10)
    const float* __restrict__ nf,     // (N, 32, 4)
    const float* __restrict__ Wskip,  // (2, 32, 10, 32)
    const float* __restrict__ Wfirst, // (2, 32, 32)
    float* __restrict__ out_sc)       // out + NN*128
{
    extern __shared__ float s[];
    for (int t = threadIdx.x; t < 10240; t += blockDim.x) {
        int c = t / 320; int v = (t / 32) % 10; int w = t & 31;
        int dst = ((c * 5 + (v >> 1)) * 32 + w) * 2 + (v & 1);
        s[dst]         = Wskip[t];
        s[10240 + dst] = Wskip[10240 + t];
    }
    for (int t = threadIdx.x; t < 2048; t += blockDim.x) {
        int skip = t >> 10; int r = t & 1023; int d = r >> 5; int c = r & 31;
        s[20480 + skip * 1024 + c * 32 + d] = Wfirst[t];
    }
    __syncthreads();
    const float2* sW0p = (const float2*)s;
    const float2* sW1p = (const float2*)(s + 10240);
    const float*  sWfT = s + 20480;

    int lane  = threadIdx.x & 31;
    int warp  = threadIdx.x >> 5;
    int nwarp = (blockDim.x >> 5) * gridDim.x;
    const int NT = NN / 2;

    for (int t = blockIdx.x * (blockDim.x >> 5) + warp; t < NT; t += nwarp) {
        int n0 = 2 * t, n1 = 2 * t + 1;
        float2 na0[5], na1[5];
        #pragma unroll
        for (int vp = 0; vp < 5; vp++) {
            na0[vp] = make_float2(na[n0 * 10 + 2 * vp], na[n0 * 10 + 2 * vp + 1]);
            na1[vp] = make_float2(na[n1 * 10 + 2 * vp], na[n1 * 10 + 2 * vp + 1]);
        }
        const float4* f0 = (const float4*)(nf + (size_t)n0 * 128);
        const float4* f1 = (const float4*)(nf + (size_t)n1 * 128);

        float sc0_0 = 0.f, sc1_0 = 0.f, sc2_0 = 0.f, sc3_0 = 0.f;
        float sc0_1 = 0.f, sc1_1 = 0.f, sc2_1 = 0.f, sc3_1 = 0.f;
        float x0_0 = 0.f, x1_0 = 0.f, x2_0 = 0.f, x3_0 = 0.f;
        float x0_1 = 0.f, x1_1 = 0.f, x2_1 = 0.f, x3_1 = 0.f;

        #pragma unroll 4
        for (int c = 0; c < 32; c++) {
            float4 fa = f0[c];
            float4 fb = f1[c];
            float A0 = 0.f, B0 = 0.f, A1 = 0.f, B1 = 0.f;
            #pragma unroll
            for (int vp = 0; vp < 5; vp++) {
                float2 W0 = sW0p[(c * 5 + vp) * 32 + lane];
                float2 W1 = sW1p[(c * 5 + vp) * 32 + lane];
                A0 += na0[vp].x * W0.x + na0[vp].y * W0.y;
                B0 += na0[vp].x * W1.x + na0[vp].y * W1.y;
                A1 += na1[vp].x * W0.x + na1[vp].y * W0.y;
                B1 += na1[vp].x * W1.x + na1[vp].y * W1.y;
            }
            sc0_0 += fa.x * A0; sc1_0 += fa.y * B0; sc2_0 += fa.z * B0; sc3_0 += fa.w * B0;
            sc0_1 += fb.x * A1; sc1_1 += fb.y * B1; sc2_1 += fb.z * B1; sc3_1 += fb.w * B1;
            float w0 = sWfT[c * 32 + lane];
            float w1 = sWfT[1024 + c * 32 + lane];
            x0_0 += fa.x * w0; x1_0 += fa.y * w1; x2_0 += fa.z * w1; x3_0 += fa.w * w1;
            x0_1 += fb.x * w0; x1_1 += fb.y * w1; x2_1 += fb.z * w1; x3_1 += fb.w * w1;
        }
        const float s320 = 0.05590169943749474f;
        const float sC   = 0.17677669529663687f;
        *(float4*)(out_sc + (size_t)n0 * 128 + lane * 4) =
            make_float4(sc0_0 * s320, sc1_0 * s320, sc2_0 * s320, sc3_0 * s320);
        *(float4*)(out_sc + (size_t)n1 * 128 + lane * 4) =
            make_float4(sc0_1 * s320, sc1_1 * s320, sc2_1 * s320, sc3_1 * s320);
        float* xo0 = g_X + (size_t)n0 * 128;
        xo0[lane] = x0_0 * sC; xo0[32 + lane] = x1_0 * sC;
        xo0[64 + lane] = x2_0 * sC; xo0[96 + lane] = x3_0 * sC;
        float* xo1 = g_X + (size_t)n1 * 128;
        xo1[lane] = x0_1 * sC; xo1[32 + lane] = x1_1 * sC;
        xo1[64 + lane] = x2_1 * sC; xo1[96 + lane] = x3_1 * sC;
    }
}

// ---------------------------------------------------------------------------
// act + split-pack D[8][4] back into bf16 h/l staging
// ---------------------------------------------------------------------------
__device__ __forceinline__ void act_store(float D[8][4], float scale,
                                          u32* stgH, u32* stgL, int g, int tq)
{
    __syncwarp();
    #pragma unroll
    for (int nt = 0; nt < 8; nt++) {
        float v0 = act(D[nt][0] * scale), v1 = act(D[nt][1] * scale);
        float v2 = act(D[nt][2] * scale), v3 = act(D[nt][3] * scale);
        uint2 p01 = bsplit2(v0, v1);
        uint2 p23 = bsplit2(v2, v3);
        stgH[g * STR + nt * 4 + tq]       = p01.x;
        stgL[g * STR + nt * 4 + tq]       = p01.y;
        stgH[(g + 8) * STR + nt * 4 + tq] = p23.x;
        stgL[(g + 8) * STR + nt * 4 + tq] = p23.y;
    }
    __syncwarp();
}

// 64->64 layer via mma (3-term bf16 split)
__device__ __forceinline__ void layer_mma(const uint4* __restrict__ sB,
                                          u32* stgH, u32* stgL,
                                          int lane, int g, int tq, float scale)
{
    float D[8][4];
    #pragma unroll
    for (int nt = 0; nt < 8; nt++)
        D[nt][0] = D[nt][1] = D[nt][2] = D[nt][3] = 0.f;
    #pragma unroll
    for (int kt = 0; kt < 4; kt++) {
        u32 Ah0 = stgH[g * STR + kt * 8 + tq];
        u32 Ah1 = stgH[(g + 8) * STR + kt * 8 + tq];
        u32 Ah2 = stgH[g * STR + kt * 8 + tq + 4];
        u32 Ah3 = stgH[(g + 8) * STR + kt * 8 + tq + 4];
        u32 Al0 = stgL[g * STR + kt * 8 + tq];
        u32 Al1 = stgL[(g + 8) * STR + kt * 8 + tq];
        u32 Al2 = stgL[g * STR + kt * 8 + tq + 4];
        u32 Al3 = stgL[(g + 8) * STR + kt * 8 + tq + 4];
        #pragma unroll
        for (int nt = 0; nt < 8; nt++) {
            uint4 B = sB[(kt * 8 + nt) * 32 + lane];
            mma16816(D[nt], Ah0, Ah1, Ah2, Ah3, B.x, B.y);
            mma16816(D[nt], Al0, Al1, Al2, Al3, B.x, B.y);
            mma16816(D[nt], Ah0, Ah1, Ah2, Ah3, B.z, B.w);
        }
    }
    act_store(D, scale, stgH, stgL, g, tq);
}

// ---------------------------------------------------------------------------
// K2: edge MLP on tensor cores (16 edges/warp tile) + scalar epilogue
// 12 warps/CTA, grid=148 (one wave), conflict-free staging
// ---------------------------------------------------------------------------
#define KE_WARPS 12
#define KE_THREADS (KE_WARPS * 32)
// per-warp staging: 2624 floats. smem = 19456 + 12*2624 = 50944 floats = 203776 B
#define KE_SMEM_FLOATS (19456 + KE_WARPS * 2624)

__global__ void __launch_bounds__(KE_THREADS, 1) k_edge(
    const float* __restrict__ ef,     // (E, 8)
    const float* __restrict__ ea,     // (E, 1, 4)
    const int*   __restrict__ idx_i,  // (E,) sorted
    const int*   __restrict__ idx_j,  // (E,)
    const float* __restrict__ Wr0,    // (64, 8)
    const float* __restrict__ Wr1,    // (64, 64)
    const float* __restrict__ Wr2,    // (64, 64)
    const float* __restrict__ Wr3)    // (160, 64)
{
    extern __shared__ float s[];
    uint4* sB0 = (uint4*)s;            // [0,1024) floats
    uint4* sB1 = (uint4*)(s + 1024);   // [1024,5120)
    uint4* sB2 = (uint4*)(s + 5120);   // [5120,9216)
    uint4* sB3 = (uint4*)(s + 9216);   // [9216,19456)

    int tid  = threadIdx.x;
    int lane = tid & 31;
    int g    = lane >> 2;     // mma group row
    int tq   = lane & 3;      // mma thread-in-group

    // ---- prepack weights into fragment-ready {bh0,bh1,bl0,bl1} uint4s
    for (int t = tid; t < 256; t += KE_THREADS) {
        int nt = t >> 5;
        int gg = (t >> 2) & 7, tt = t & 3;
        int j = nt * 8 + gg, kb = 2 * tt;
        uint2 P0 = bsplit2(Wr0[j * 8 + kb], Wr0[j * 8 + kb + 1]);
        sB0[t] = make_uint4(P0.x, 0u, P0.y, 0u);     // K rows 8..15 are zero
    }
    for (int t = tid; t < 1024; t += KE_THREADS) {
        int kt = t >> 8, nt = (t >> 5) & 7;
        int gg = (t >> 2) & 7, tt = t & 3;
        int j = nt * 8 + gg, kb = kt * 16 + 2 * tt;
        {
            uint2 P0 = bsplit2(Wr1[j * 64 + kb],     Wr1[j * 64 + kb + 1]);
            uint2 P1 = bsplit2(Wr1[j * 64 + kb + 8], Wr1[j * 64 + kb + 9]);
            sB1[t] = make_uint4(P0.x, P1.x, P0.y, P1.y);
        }
        {
            uint2 P0 = bsplit2(Wr2[j * 64 + kb],     Wr2[j * 64 + kb + 1]);
            uint2 P1 = bsplit2(Wr2[j * 64 + kb + 8], Wr2[j * 64 + kb + 9]);
            sB2[t] = make_uint4(P0.x, P1.x, P0.y, P1.y);
        }
    }
    for (int t = tid; t < 2560; t += KE_THREADS) {
        int kt = t / 640, rem = t % 640;
        int nt = rem >> 5;
        int gg = (t >> 2) & 7, tt = t & 3;
        int j = nt * 8 + gg, kb = kt * 16 + 2 * tt;
        uint2 P0 = bsplit2(Wr3[j * 64 + kb],     Wr3[j * 64 + kb + 1]);
        uint2 P1 = bsplit2(Wr3[j * 64 + kb + 8], Wr3[j * 64 + kb + 9]);
        sB3[t] = make_uint4(P0.x, P1.x, P0.y, P1.y);
    }
    __syncthreads();

    int wid = tid >> 5;
    float* wbase = s + 19456 + wid * 2624;
    u32* stgH = (u32*)wbase;          // [16][STR] b32 (bf16x2 hi parts)
    u32* stgL = stgH + 16 * STR;      // [16][STR] b32 (bf16x2 residuals)
    float* stgW = wbase;              // [16][164] f32, aliases stgH/stgL in L3 phase

    int gw = blockIdx.x * KE_WARPS + wid;
    int nw = gridDim.x * KE_WARPS;
    const int NTILE = NE / 16;        // 37500
    int per = (NTILE + nw - 1) / nw;
    int t0 = gw * per;
    int t1 = (t0 + per < NTILE) ? (t0 + per) : NTILE;
    if (t0 >= t1) return;

    float a0 = 0.f, a3 = 0.f;
    float a1x = 0.f, a1y = 0.f, a1z = 0.f;
    float a2x = 0.f, a2y = 0.f, a2z = 0.f;
    float a4x = 0.f, a4y = 0.f, a4z = 0.f;
    int cur = idx_i[t0 * 16];
    const float c8  = 0.35355339059327373f;
    const float c64 = 0.125f;

    for (int tile = t0; tile < t1; tile++) {
        int ebase = tile * 16;

        // ---- stage ef (16 edges x 8) as split bf16x2 pairs
        float4 v = ((const float4*)(ef + (size_t)ebase * 8))[lane];
        int se = lane >> 1, cp = (lane & 1) * 2;
        uint2 pA = bsplit2(v.x, v.y);
        uint2 pB = bsplit2(v.z, v.w);
        __syncwarp();                 // epilogue of prev tile done reading stgW
        stgH[se * STR + cp]     = pA.x; stgL[se * STR + cp]     = pA.y;
        stgH[se * STR + cp + 1] = pB.x; stgL[se * STR + cp + 1] = pB.y;
        __syncwarp();

        // ---- L0: 8 -> 64 (K=8, upper half zero)
        {
            float D[8][4];
            #pragma unroll
            for (int nt = 0; nt < 8; nt++)
                D[nt][0] = D[nt][1] = D[nt][2] = D[nt][3] = 0.f;
            u32 Ah0 = stgH[g * STR + tq];
            u32 Ah1 = stgH[(g + 8) * STR + tq];
            u32 Al0 = stgL[g * STR + tq];
            u32 Al1 = stgL[(g + 8) * STR + tq];
            #pragma unroll
            for (int nt = 0; nt < 8; nt++) {
                uint4 B = sB0[nt * 32 + lane];
                mma16816(D[nt], Ah0, Ah1, 0u, 0u, B.x, B.y);
                mma16816(D[nt], Al0, Al1, 0u, 0u, B.x, B.y);
                mma16816(D[nt], Ah0, Ah1, 0u, 0u, B.z, B.w);
            }
            act_store(D, c8, stgH, stgL, g, tq);
        }

        // ---- L1, L2: 64 -> 64
        layer_mma(sB1, stgH, stgL, lane, g, tq, c64);
        layer_mma(sB2, stgH, stgL, lane, g, tq, c64);

        // ---- L3: 64 -> 160, preload A frags then two 80-col halves
        u32 Ah[4][4], Al[4][4];
        #pragma unroll
        for (int kt = 0; kt < 4; kt++) {
            Ah[kt][0] = stgH[g * STR + kt * 8 + tq];
            Ah[kt][1] = stgH[(g + 8) * STR + kt * 8 + tq];
            Ah[kt][2] = stgH[g * STR + kt * 8 + tq + 4];
            Ah[kt][3] = stgH[(g + 8) * STR + kt * 8 + tq + 4];
            Al[kt][0] = stgL[g * STR + kt * 8 + tq];
            Al[kt][1] = stgL[(g + 8) * STR + kt * 8 + tq];
            Al[kt][2] = stgL[g * STR + kt * 8 + tq + 4];
            Al[kt][3] = stgL[(g + 8) * STR + kt * 8 + tq + 4];
        }
        __syncwarp();                 // all A reads done before stgW overwrite

        #pragma unroll
        for (int half = 0; half < 2; half++) {
            float D3[10][4];
            #pragma unroll
            for (int nt = 0; nt < 10; nt++)
                D3[nt][0] = D3[nt][1] = D3[nt][2] = D3[nt][3] = 0.f;
            #pragma unroll
            for (int kt = 0; kt < 4; kt++) {
                #pragma unroll
                for (int nt = 0; nt < 10; nt++) {
                    uint4 B = sB3[(kt * 20 + half * 10 + nt) * 32 + lane];
                    mma16816(D3[nt], Ah[kt][0], Ah[kt][1], Ah[kt][2], Ah[kt][3], B.x, B.y);
                    mma16816(D3[nt], Al[kt][0], Al[kt][1], Al[kt][2], Al[kt][3], B.x, B.y);
                    mma16816(D3[nt], Ah[kt][0], Ah[kt][1], Ah[kt][2], Ah[kt][3], B.z, B.w);
                }
            }
            #pragma unroll
            for (int nt = 0; nt < 10; nt++) {
                int col = (half * 10 + nt) * 8 + 2 * tq;
                *(float2*)&stgW[g * 164 + col] =
                    make_float2(D3[nt][0] * c64, D3[nt][1] * c64);
                *(float2*)&stgW[(g + 8) * 164 + col] =
                    make_float2(D3[nt][2] * c64, D3[nt][3] * c64);
            }
        }
        __syncwarp();

        // ---- epilogue: 4 sub-batches of 4 edges
        #pragma unroll
        for (int sb = 0; sb < 4; sb++) {
            int4 ii = *(const int4*)(idx_i + ebase + sb * 4);
            int4 jj = *(const int4*)(idx_j + ebase + sb * 4);
            int iarr[4] = {ii.x, ii.y, ii.z, ii.w};
            int jarr[4] = {jj.x, jj.y, jj.z, jj.w};

            #pragma unroll
            for (int r = 0; r < 4; r++) {
                int ni = iarr[r];
                if (ni != cur) {
                    atomicAdd(&g_M0[(size_t)cur * 64 + lane],      a0);
                    atomicAdd(&g_M0[(size_t)cur * 64 + 32 + lane], a3);
                    float* m1 = g_M1 + (size_t)cur * 288 + lane;
                    atomicAdd(m1 + 0,   a1x); atomicAdd(m1 + 32,  a1y); atomicAdd(m1 + 64,  a1z);
                    atomicAdd(m1 + 96,  a2x); atomicAdd(m1 + 128, a2y); atomicAdd(m1 + 160, a2z);
                    atomicAdd(m1 + 192, a4x); atomicAdd(m1 + 224, a4y); atomicAdd(m1 + 256, a4z);
                    a0 = a3 = a1x = a1y = a1z = a2x = a2y = a2z = a4x = a4y = a4z = 0.f;
                    cur = ni;
                }
                int e = sb * 4 + r;
                int eg = ebase + e;
                int j = jarr[r];
                const float* xb = g_X + (size_t)j * 128;
                float xj0 = xb[lane];
                float xa  = xb[32 + lane];
                float xbv = xb[64 + lane];
                float xc  = xb[96 + lane];
                float4 y = *(const float4*)(ea + (size_t)eg * 4);

                const float* W = stgW + e * 164;
                float v0 = W[lane];
                float v1 = W[32 + lane];
                float v2 = W[64 + lane];
                float v3 = W[96 + lane];
                float v4 = W[128 + lane];

                a0 += v0 * xj0 * y.x;
                float t1 = v1 * xj0;
                a1x += t1 * y.y; a1y += t1 * y.z; a1z += t1 * y.w;
                a2x += v2 * xa * y.x; a2y += v2 * xbv * y.x; a2z += v2 * xc * y.x;
                a3  += v3 * (xa * y.y + xbv * y.z + xc * y.w);
                a4x += v4 * (xbv * y.w - xc * y.z);
                a4y += v4 * (xc * y.y - xa * y.w);
                a4z += v4 * (xa * y.z - xbv * y.y);
            }
        }
    }
    // final flush
    atomicAdd(&g_M0[(size_t)cur * 64 + lane],      a0);
    atomicAdd(&g_M0[(size_t)cur * 64 + 32 + lane], a3);
    float* m1 = g_M1 + (size_t)cur * 288 + lane;
    atomicAdd(m1 + 0,   a1x); atomicAdd(m1 + 32,  a1y); atomicAdd(m1 + 64,  a1z);
    atomicAdd(m1 + 96,  a2x); atomicAdd(m1 + 128, a2y); atomicAdd(m1 + 160, a2z);
    atomicAdd(m1 + 192, a4x); atomicAdd(m1 + 224, a4y); atomicAdd(m1 + 256, a4z);
}

// ---------------------------------------------------------------------------
// K3: per-node second linear -> message output (unchanged)
// ---------------------------------------------------------------------------
__global__ void __launch_bounds__(128) k_out(
    const float* __restrict__ Ws0,  // (32, 64)
    const float* __restrict__ Ws1,  // (32, 96)
    float* __restrict__ out)
{
    __shared__ float sW0T[64 * 32];
    __shared__ float sW1T[96 * 32];
    for (int t = threadIdx.x; t < 2048; t += blockDim.x) {
        int d = t >> 6, k = t & 63;
        sW0T[k * 32 + d] = Ws0[t];
    }
    for (int t = threadIdx.x; t < 3072; t += blockDim.x) {
        int d = t / 96, k = t % 96;
        sW1T[k * 32 + d] = Ws1[t];
    }
    __syncthreads();

    int lane  = threadIdx.x & 31;
    int warp  = threadIdx.x >> 5;
    int nwarp = (blockDim.x >> 5) * gridDim.x;
    const float sA  = 1.0f / 12.0f;
    const float s64 = 0.125f;
    const float s96 = 0.10206207261596575f;

    for (int n = blockIdx.x * (blockDim.x >> 5) + warp; n < NN; n += nwarp) {
        const float4* m0 = (const float4*)(g_M0 + (size_t)n * 64);
        float o0 = 0.f;
        #pragma unroll
        for (int t = 0; t < 16; t++) {
            float4 v = m0[t];
            o0 += v.x * sW0T[(t * 4 + 0) * 32 + lane]
                + v.y * sW0T[(t * 4 + 1) * 32 + lane]
                + v.z * sW0T[(t * 4 + 2) * 32 + lane]
                + v.w * sW0T[(t * 4 + 3) * 32 + lane];
        }
        float o1x = 0.f, o1y = 0.f, o1z = 0.f;
        #pragma unroll
        for (int p = 0; p < 3; p++) {
            const float4* m1 = (const float4*)(g_M1 + (size_t)n * 288 + p * 96);
            #pragma unroll
            for (int q = 0; q < 8; q++) {
                float4 vx = m1[q];
                float4 vy = m1[8 + q];
                float4 vz = m1[16 + q];
                float wA = sW1T[(p * 32 + q * 4 + 0) * 32 + lane];
                float wB = sW1T[(p * 32 + q * 4 + 1) * 32 + lane];
                float wC = sW1T[(p * 32 + q * 4 + 2) * 32 + lane];
                float wD = sW1T[(p * 32 + q * 4 + 3) * 32 + lane];
                o1x += vx.x * wA + vx.y * wB + vx.z * wC + vx.w * wD;
                o1y += vy.x * wA + vy.y * wB + vy.z * wC + vy.w * wD;
                o1z += vz.x * wA + vz.y * wB + vz.z * wC + vz.w * wD;
            }
        }
        float4 r = make_float4(o0 * s64 * sA, o1x * s96 * sA, o1y * s96 * sA, o1z * s96 * sA);
        *(float4*)(out + (size_t)n * 128 + lane * 4) = r;
    }
}

// ---------------------------------------------------------------------------
extern "C" void kernel_launch(void* const* d_in, const int* in_sizes, int n_in,
                              void* d_out, int out_size)
{
    const float* na     = (const float*)d_in[0];
    const float* nf     = (const float*)d_in[1];
    const float* ea     = (const float*)d_in[2];
    const float* ef     = (const float*)d_in[3];
    const float* Wfirst = (const float*)d_in[4];
    const float* Wr0    = (const float*)d_in[5];
    const float* Wr1    = (const float*)d_in[6];
    const float* Wr2    = (const float*)d_in[7];
    const float* Wr3    = (const float*)d_in[8];
    const float* Ws0    = (const float*)d_in[9];
    const float* Ws1    = (const float*)d_in[10];
    const float* Wskip  = (const float*)d_in[11];
    const int*   idx_i  = (const int*)d_in[12];
    const int*   idx_j  = (const int*)d_in[13];
    float* out = (float*)d_out;

    cudaFuncSetAttribute(k_node, cudaFuncAttributeMaxDynamicSharedMemorySize, 22528 * 4);
    cudaFuncSetAttribute(k_edge, cudaFuncAttributeMaxDynamicSharedMemorySize, KE_SMEM_FLOATS * 4);

    void *pM0, *pM1;
    cudaGetSymbolAddress(&pM0, g_M0);
    cudaGetSymbolAddress(&pM1, g_M1);
    cudaMemsetAsync(pM0, 0, sizeof(float) * NN * 64, 0);
    cudaMemsetAsync(pM1, 0, sizeof(float) * NN * 288, 0);

    k_node<<<296, 512, 22528 * 4>>>(na, nf, Wskip, Wfirst, out + (size_t)NN * 128);
    k_edge<<<148, KE_THREADS, KE_SMEM_FLOATS * 4>>>(ef, ea, idx_i, idx_j, Wr0, Wr1, Wr2, Wr3);
    k_out<<<592, 128>>>(Ws0, Ws1, out);
}

// round 13
// speedup vs baseline: 1.0041x; 1.0041x over previous
#include <cuda_runtime.h>
#include <cuda_bf16.h>
#include <math.h>

#define NN 50000
#define NE 600000

typedef unsigned int u32;

// Scratch (allocation-free: static __device__ globals)
__device__ float g_X [NN * 128];   // [n][m(0..3)][c]
__device__ float g_M0[NN * 64];    // [n][s(0:p0,1:p3)][c]
__device__ float g_M1[NN * 288];   // [n][p(0:p1,1:p2,2:p4)][m(0..2)][c]

__device__ __forceinline__ float act(float x) {
    return 1.6765324703310907f * x * (1.0f / (1.0f + __expf(-x)));
}

// split-pack a pair (v0 -> low half, v1 -> high half): {hi bf16x2, residual bf16x2}
__device__ __forceinline__ uint2 bsplit2(float v0, float v1) {
    u32 h;
    asm("cvt.rn.bf16x2.f32 %0, %1, %2;" : "=r"(h) : "f"(v1), "f"(v0));
    float h0 = __uint_as_float(h << 16);
    float h1 = __uint_as_float(h & 0xFFFF0000u);
    float r0 = v0 - h0, r1 = v1 - h1;
    u32 l;
    asm("cvt.rn.bf16x2.f32 %0, %1, %2;" : "=r"(l) : "f"(r1), "f"(r0));
    return make_uint2(h, l);
}

__device__ __forceinline__ void mma16816(float* d, u32 a0, u32 a1, u32 a2, u32 a3,
                                         u32 b0, u32 b1) {
    asm("mma.sync.aligned.m16n8k16.row.col.f32.bf16.bf16.f32 "
        "{%0,%1,%2,%3}, {%4,%5,%6,%7}, {%8,%9}, {%0,%1,%2,%3};"
        : "+f"(d[0]), "+f"(d[1]), "+f"(d[2]), "+f"(d[3])
        : "r"(a0), "r"(a1), "r"(a2), "r"(a3), "r"(b0), "r"(b1));
}

#define STR 36   // staging row stride (u32): bank = (4g+tq)%32, conflict-free

// ---------------------------------------------------------------------------
// K1: per-node skip + first linear. 2 nodes per warp iteration. (unchanged)
// ---------------------------------------------------------------------------
__global__ void __launch_bounds__(512) k_node(
    const float* __restrict__ na,     // (N, 10)
    const float* __restrict__ nf,     // (N, 32, 4)
    const float* __restrict__ Wskip,  // (2, 32, 10, 32)
    const float* __restrict__ Wfirst, // (2, 32, 32)
    float* __restrict__ out_sc)       // out + NN*128
{
    extern __shared__ float s[];
    for (int t = threadIdx.x; t < 10240; t += blockDim.x) {
        int c = t / 320; int v = (t / 32) % 10; int w = t & 31;
        int dst = ((c * 5 + (v >> 1)) * 32 + w) * 2 + (v & 1);
        s[dst]         = Wskip[t];
        s[10240 + dst] = Wskip[10240 + t];
    }
    for (int t = threadIdx.x; t < 2048; t += blockDim.x) {
        int skip = t >> 10; int r = t & 1023; int d = r >> 5; int c = r & 31;
        s[20480 + skip * 1024 + c * 32 + d] = Wfirst[t];
    }
    __syncthreads();
    const float2* sW0p = (const float2*)s;
    const float2* sW1p = (const float2*)(s + 10240);
    const float*  sWfT = s + 20480;

    int lane  = threadIdx.x & 31;
    int warp  = threadIdx.x >> 5;
    int nwarp = (blockDim.x >> 5) * gridDim.x;
    const int NT = NN / 2;

    for (int t = blockIdx.x * (blockDim.x >> 5) + warp; t < NT; t += nwarp) {
        int n0 = 2 * t, n1 = 2 * t + 1;
        float2 na0[5], na1[5];
        #pragma unroll
        for (int vp = 0; vp < 5; vp++) {
            na0[vp] = make_float2(na[n0 * 10 + 2 * vp], na[n0 * 10 + 2 * vp + 1]);
            na1[vp] = make_float2(na[n1 * 10 + 2 * vp], na[n1 * 10 + 2 * vp + 1]);
        }
        const float4* f0 = (const float4*)(nf + (size_t)n0 * 128);
        const float4* f1 = (const float4*)(nf + (size_t)n1 * 128);

        float sc0_0 = 0.f, sc1_0 = 0.f, sc2_0 = 0.f, sc3_0 = 0.f;
        float sc0_1 = 0.f, sc1_1 = 0.f, sc2_1 = 0.f, sc3_1 = 0.f;
        float x0_0 = 0.f, x1_0 = 0.f, x2_0 = 0.f, x3_0 = 0.f;
        float x0_1 = 0.f, x1_1 = 0.f, x2_1 = 0.f, x3_1 = 0.f;

        #pragma unroll 4
        for (int c = 0; c < 32; c++) {
            float4 fa = f0[c];
            float4 fb = f1[c];
            float A0 = 0.f, B0 = 0.f, A1 = 0.f, B1 = 0.f;
            #pragma unroll
            for (int vp = 0; vp < 5; vp++) {
                float2 W0 = sW0p[(c * 5 + vp) * 32 + lane];
                float2 W1 = sW1p[(c * 5 + vp) * 32 + lane];
                A0 += na0[vp].x * W0.x + na0[vp].y * W0.y;
                B0 += na0[vp].x * W1.x + na0[vp].y * W1.y;
                A1 += na1[vp].x * W0.x + na1[vp].y * W0.y;
                B1 += na1[vp].x * W1.x + na1[vp].y * W1.y;
            }
            sc0_0 += fa.x * A0; sc1_0 += fa.y * B0; sc2_0 += fa.z * B0; sc3_0 += fa.w * B0;
            sc0_1 += fb.x * A1; sc1_1 += fb.y * B1; sc2_1 += fb.z * B1; sc3_1 += fb.w * B1;
            float w0 = sWfT[c * 32 + lane];
            float w1 = sWfT[1024 + c * 32 + lane];
            x0_0 += fa.x * w0; x1_0 += fa.y * w1; x2_0 += fa.z * w1; x3_0 += fa.w * w1;
            x0_1 += fb.x * w0; x1_1 += fb.y * w1; x2_1 += fb.z * w1; x3_1 += fb.w * w1;
        }
        const float s320 = 0.05590169943749474f;
        const float sC   = 0.17677669529663687f;
        *(float4*)(out_sc + (size_t)n0 * 128 + lane * 4) =
            make_float4(sc0_0 * s320, sc1_0 * s320, sc2_0 * s320, sc3_0 * s320);
        *(float4*)(out_sc + (size_t)n1 * 128 + lane * 4) =
            make_float4(sc0_1 * s320, sc1_1 * s320, sc2_1 * s320, sc3_1 * s320);
        float* xo0 = g_X + (size_t)n0 * 128;
        xo0[lane] = x0_0 * sC; xo0[32 + lane] = x1_0 * sC;
        xo0[64 + lane] = x2_0 * sC; xo0[96 + lane] = x3_0 * sC;
        float* xo1 = g_X + (size_t)n1 * 128;
        xo1[lane] = x0_1 * sC; xo1[32 + lane] = x1_1 * sC;
        xo1[64 + lane] = x2_1 * sC; xo1[96 + lane] = x3_1 * sC;
    }
}

// ---------------------------------------------------------------------------
// act + split-pack D[8][4] back into bf16 h/l staging
// ---------------------------------------------------------------------------
__device__ __forceinline__ void act_store(float D[8][4], float scale,
                                          u32* stgH, u32* stgL, int g, int tq)
{
    __syncwarp();
    #pragma unroll
    for (int nt = 0; nt < 8; nt++) {
        float v0 = act(D[nt][0] * scale), v1 = act(D[nt][1] * scale);
        float v2 = act(D[nt][2] * scale), v3 = act(D[nt][3] * scale);
        uint2 p01 = bsplit2(v0, v1);
        uint2 p23 = bsplit2(v2, v3);
        stgH[g * STR + nt * 4 + tq]       = p01.x;
        stgL[g * STR + nt * 4 + tq]       = p01.y;
        stgH[(g + 8) * STR + nt * 4 + tq] = p23.x;
        stgL[(g + 8) * STR + nt * 4 + tq] = p23.y;
    }
    __syncwarp();
}

// 64->64 layer via mma (3-term bf16 split)
__device__ __forceinline__ void layer_mma(const uint4* __restrict__ sB,
                                          u32* stgH, u32* stgL,
                                          int lane, int g, int tq, float scale)
{
    float D[8][4];
    #pragma unroll
    for (int nt = 0; nt < 8; nt++)
        D[nt][0] = D[nt][1] = D[nt][2] = D[nt][3] = 0.f;
    #pragma unroll
    for (int kt = 0; kt < 4; kt++) {
        u32 Ah0 = stgH[g * STR + kt * 8 + tq];
        u32 Ah1 = stgH[(g + 8) * STR + kt * 8 + tq];
        u32 Ah2 = stgH[g * STR + kt * 8 + tq + 4];
        u32 Ah3 = stgH[(g + 8) * STR + kt * 8 + tq + 4];
        u32 Al0 = stgL[g * STR + kt * 8 + tq];
        u32 Al1 = stgL[(g + 8) * STR + kt * 8 + tq];
        u32 Al2 = stgL[g * STR + kt * 8 + tq + 4];
        u32 Al3 = stgL[(g + 8) * STR + kt * 8 + tq + 4];
        #pragma unroll
        for (int nt = 0; nt < 8; nt++) {
            uint4 B = sB[(kt * 8 + nt) * 32 + lane];
            mma16816(D[nt], Ah0, Ah1, Ah2, Ah3, B.x, B.y);
            mma16816(D[nt], Al0, Al1, Al2, Al3, B.x, B.y);
            mma16816(D[nt], Ah0, Ah1, Ah2, Ah3, B.z, B.w);
        }
    }
    act_store(D, scale, stgH, stgL, g, tq);
}

// ---------------------------------------------------------------------------
// K2: edge MLP on tensor cores (16 edges/warp tile) + scalar epilogue
// 12 warps/CTA, grid=148 (one wave), conflict-free staging
// ---------------------------------------------------------------------------
#define KE_WARPS 12
#define KE_THREADS (KE_WARPS * 32)
// per-warp staging: 2624 floats. smem = 19456 + 12*2624 = 50944 floats = 203776 B
#define KE_SMEM_FLOATS (19456 + KE_WARPS * 2624)

__global__ void __launch_bounds__(KE_THREADS, 1) k_edge(
    const float* __restrict__ ef,     // (E, 8)
    const float* __restrict__ ea,     // (E, 1, 4)
    const int*   __restrict__ idx_i,  // (E,) sorted
    const int*   __restrict__ idx_j,  // (E,)
    const float* __restrict__ Wr0,    // (64, 8)
    const float* __restrict__ Wr1,    // (64, 64)
    const float* __restrict__ Wr2,    // (64, 64)
    const float* __restrict__ Wr3)    // (160, 64)
{
    extern __shared__ float s[];
    uint4* sB0 = (uint4*)s;            // [0,1024) floats
    uint4* sB1 = (uint4*)(s + 1024);   // [1024,5120)
    uint4* sB2 = (uint4*)(s + 5120);   // [5120,9216)
    uint4* sB3 = (uint4*)(s + 9216);   // [9216,19456)

    int tid  = threadIdx.x;
    int lane = tid & 31;
    int g    = lane >> 2;     // mma group row
    int tq   = lane & 3;      // mma thread-in-group

    // ---- prepack weights into fragment-ready {bh0,bh1,bl0,bl1} uint4s
    for (int t = tid; t < 256; t += KE_THREADS) {
        int nt = t >> 5;
        int gg = (t >> 2) & 7, tt = t & 3;
        int j = nt * 8 + gg, kb = 2 * tt;
        uint2 P0 = bsplit2(Wr0[j * 8 + kb], Wr0[j * 8 + kb + 1]);
        sB0[t] = make_uint4(P0.x, 0u, P0.y, 0u);     // K rows 8..15 are zero
    }
    for (int t = tid; t < 1024; t += KE_THREADS) {
        int kt = t >> 8, nt = (t >> 5) & 7;
        int gg = (t >> 2) & 7, tt = t & 3;
        int j = nt * 8 + gg, kb = kt * 16 + 2 * tt;
        {
            uint2 P0 = bsplit2(Wr1[j * 64 + kb],     Wr1[j * 64 + kb + 1]);
            uint2 P1 = bsplit2(Wr1[j * 64 + kb + 8], Wr1[j * 64 + kb + 9]);
            sB1[t] = make_uint4(P0.x, P1.x, P0.y, P1.y);
        }
        {
            uint2 P0 = bsplit2(Wr2[j * 64 + kb],     Wr2[j * 64 + kb + 1]);
            uint2 P1 = bsplit2(Wr2[j * 64 + kb + 8], Wr2[j * 64 + kb + 9]);
            sB2[t] = make_uint4(P0.x, P1.x, P0.y, P1.y);
        }
    }
    for (int t = tid; t < 2560; t += KE_THREADS) {
        int kt = t / 640, rem = t % 640;
        int nt = rem >> 5;
        int gg = (t >> 2) & 7, tt = t & 3;
        int j = nt * 8 + gg, kb = kt * 16 + 2 * tt;
        uint2 P0 = bsplit2(Wr3[j * 64 + kb],     Wr3[j * 64 + kb + 1]);
        uint2 P1 = bsplit2(Wr3[j * 64 + kb + 8], Wr3[j * 64 + kb + 9]);
        sB3[t] = make_uint4(P0.x, P1.x, P0.y, P1.y);
    }
    __syncthreads();

    int wid = tid >> 5;
    float* wbase = s + 19456 + wid * 2624;
    u32* stgH = (u32*)wbase;          // [16][STR] b32 (bf16x2 hi parts)
    u32* stgL = stgH + 16 * STR;      // [16][STR] b32 (bf16x2 residuals)
    float* stgW = wbase;              // [16][164] f32, aliases stgH/stgL in L3 phase

    int gw = blockIdx.x * KE_WARPS + wid;
    int nw = gridDim.x * KE_WARPS;
    const int NTILE = NE / 16;        // 37500
    int per = (NTILE + nw - 1) / nw;
    int t0 = gw * per;
    int t1 = (t0 + per < NTILE) ? (t0 + per) : NTILE;
    if (t0 >= t1) return;

    float a0 = 0.f, a3 = 0.f;
    float a1x = 0.f, a1y = 0.f, a1z = 0.f;
    float a2x = 0.f, a2y = 0.f, a2z = 0.f;
    float a4x = 0.f, a4y = 0.f, a4z = 0.f;
    int cur = idx_i[t0 * 16];
    const float c8  = 0.35355339059327373f;
    const float c64 = 0.125f;

    for (int tile = t0; tile < t1; tile++) {
        int ebase = tile * 16;

        // ---- stage ef (16 edges x 8) as split bf16x2 pairs
        float4 v = ((const float4*)(ef + (size_t)ebase * 8))[lane];
        int se = lane >> 1, cp = (lane & 1) * 2;
        uint2 pA = bsplit2(v.x, v.y);
        uint2 pB = bsplit2(v.z, v.w);
        __syncwarp();                 // epilogue of prev tile done reading stgW
        stgH[se * STR + cp]     = pA.x; stgL[se * STR + cp]     = pA.y;
        stgH[se * STR + cp + 1] = pB.x; stgL[se * STR + cp + 1] = pB.y;
        __syncwarp();

        // ---- L0: 8 -> 64 (K=8, upper half zero)
        {
            float D[8][4];
            #pragma unroll
            for (int nt = 0; nt < 8; nt++)
                D[nt][0] = D[nt][1] = D[nt][2] = D[nt][3] = 0.f;
            u32 Ah0 = stgH[g * STR + tq];
            u32 Ah1 = stgH[(g + 8) * STR + tq];
            u32 Al0 = stgL[g * STR + tq];
            u32 Al1 = stgL[(g + 8) * STR + tq];
            #pragma unroll
            for (int nt = 0; nt < 8; nt++) {
                uint4 B = sB0[nt * 32 + lane];
                mma16816(D[nt], Ah0, Ah1, 0u, 0u, B.x, B.y);
                mma16816(D[nt], Al0, Al1, 0u, 0u, B.x, B.y);
                mma16816(D[nt], Ah0, Ah1, 0u, 0u, B.z, B.w);
            }
            act_store(D, c8, stgH, stgL, g, tq);
        }

        // ---- L1, L2: 64 -> 64
        layer_mma(sB1, stgH, stgL, lane, g, tq, c64);
        layer_mma(sB2, stgH, stgL, lane, g, tq, c64);

        // ---- L3: 64 -> 160, preload A frags then two 80-col halves
        u32 Ah[4][4], Al[4][4];
        #pragma unroll
        for (int kt = 0; kt < 4; kt++) {
            Ah[kt][0] = stgH[g * STR + kt * 8 + tq];
            Ah[kt][1] = stgH[(g + 8) * STR + kt * 8 + tq];
            Ah[kt][2] = stgH[g * STR + kt * 8 + tq + 4];
            Ah[kt][3] = stgH[(g + 8) * STR + kt * 8 + tq + 4];
            Al[kt][0] = stgL[g * STR + kt * 8 + tq];
            Al[kt][1] = stgL[(g + 8) * STR + kt * 8 + tq];
            Al[kt][2] = stgL[g * STR + kt * 8 + tq + 4];
            Al[kt][3] = stgL[(g + 8) * STR + kt * 8 + tq + 4];
        }
        __syncwarp();                 // all A reads done before stgW overwrite

        #pragma unroll
        for (int half = 0; half < 2; half++) {
            float D3[10][4];
            #pragma unroll
            for (int nt = 0; nt < 10; nt++)
                D3[nt][0] = D3[nt][1] = D3[nt][2] = D3[nt][3] = 0.f;
            #pragma unroll
            for (int kt = 0; kt < 4; kt++) {
                #pragma unroll
                for (int nt = 0; nt < 10; nt++) {
                    uint4 B = sB3[(kt * 20 + half * 10 + nt) * 32 + lane];
                    mma16816(D3[nt], Ah[kt][0], Ah[kt][1], Ah[kt][2], Ah[kt][3], B.x, B.y);
                    mma16816(D3[nt], Al[kt][0], Al[kt][1], Al[kt][2], Al[kt][3], B.x, B.y);
                    mma16816(D3[nt], Ah[kt][0], Ah[kt][1], Ah[kt][2], Ah[kt][3], B.z, B.w);
                }
            }
            #pragma unroll
            for (int nt = 0; nt < 10; nt++) {
                int col = (half * 10 + nt) * 8 + 2 * tq;
                *(float2*)&stgW[g * 164 + col] =
                    make_float2(D3[nt][0] * c64, D3[nt][1] * c64);
                *(float2*)&stgW[(g + 8) * 164 + col] =
                    make_float2(D3[nt][2] * c64, D3[nt][3] * c64);
            }
        }
        __syncwarp();

        // ---- epilogue: 4 sub-batches of 4 edges
        #pragma unroll
        for (int sb = 0; sb < 4; sb++) {
            int4 ii = *(const int4*)(idx_i + ebase + sb * 4);
            int4 jj = *(const int4*)(idx_j + ebase + sb * 4);
            int iarr[4] = {ii.x, ii.y, ii.z, ii.w};
            int jarr[4] = {jj.x, jj.y, jj.z, jj.w};

            #pragma unroll
            for (int r = 0; r < 4; r++) {
                int ni = iarr[r];
                if (ni != cur) {
                    atomicAdd(&g_M0[(size_t)cur * 64 + lane],      a0);
                    atomicAdd(&g_M0[(size_t)cur * 64 + 32 + lane], a3);
                    float* m1 = g_M1 + (size_t)cur * 288 + lane;
                    atomicAdd(m1 + 0,   a1x); atomicAdd(m1 + 32,  a1y); atomicAdd(m1 + 64,  a1z);
                    atomicAdd(m1 + 96,  a2x); atomicAdd(m1 + 128, a2y); atomicAdd(m1 + 160, a2z);
                    atomicAdd(m1 + 192, a4x); atomicAdd(m1 + 224, a4y); atomicAdd(m1 + 256, a4z);
                    a0 = a3 = a1x = a1y = a1z = a2x = a2y = a2z = a4x = a4y = a4z = 0.f;
                    cur = ni;
                }
                int e = sb * 4 + r;
                int eg = ebase + e;
                int j = jarr[r];
                const float* xb = g_X + (size_t)j * 128;
                float xj0 = xb[lane];
                float xa  = xb[32 + lane];
                float xbv = xb[64 + lane];
                float xc  = xb[96 + lane];
                float4 y = *(const float4*)(ea + (size_t)eg * 4);

                const float* W = stgW + e * 164;
                float v0 = W[lane];
                float v1 = W[32 + lane];
                float v2 = W[64 + lane];
                float v3 = W[96 + lane];
                float v4 = W[128 + lane];

                a0 += v0 * xj0 * y.x;
                float t1 = v1 * xj0;
                a1x += t1 * y.y; a1y += t1 * y.z; a1z += t1 * y.w;
                a2x += v2 * xa * y.x; a2y += v2 * xbv * y.x; a2z += v2 * xc * y.x;
                a3  += v3 * (xa * y.y + xbv * y.z + xc * y.w);
                a4x += v4 * (xbv * y.w - xc * y.z);
                a4y += v4 * (xc * y.y - xa * y.w);
                a4z += v4 * (xa * y.z - xbv * y.y);
            }
        }
    }
    // final flush
    atomicAdd(&g_M0[(size_t)cur * 64 + lane],      a0);
    atomicAdd(&g_M0[(size_t)cur * 64 + 32 + lane], a3);
    float* m1 = g_M1 + (size_t)cur * 288 + lane;
    atomicAdd(m1 + 0,   a1x); atomicAdd(m1 + 32,  a1y); atomicAdd(m1 + 64,  a1z);
    atomicAdd(m1 + 96,  a2x); atomicAdd(m1 + 128, a2y); atomicAdd(m1 + 160, a2z);
    atomicAdd(m1 + 192, a4x); atomicAdd(m1 + 224, a4y); atomicAdd(m1 + 256, a4z);
}

// ---------------------------------------------------------------------------
// K3: per-node second linear -> message output (unchanged)
// ---------------------------------------------------------------------------
__global__ void __launch_bounds__(128) k_out(
    const float* __restrict__ Ws0,  // (32, 64)
    const float* __restrict__ Ws1,  // (32, 96)
    float* __restrict__ out)
{
    __shared__ float sW0T[64 * 32];
    __shared__ float sW1T[96 * 32];
    for (int t = threadIdx.x; t < 2048; t += blockDim.x) {
        int d = t >> 6, k = t & 63;
        sW0T[k * 32 + d] = Ws0[t];
    }
    for (int t = threadIdx.x; t < 3072; t += blockDim.x) {
        int d = t / 96, k = t % 96;
        sW1T[k * 32 + d] = Ws1[t];
    }
    __syncthreads();

    int lane  = threadIdx.x & 31;
    int warp  = threadIdx.x >> 5;
    int nwarp = (blockDim.x >> 5) * gridDim.x;
    const float sA  = 1.0f / 12.0f;
    const float s64 = 0.125f;
    const float s96 = 0.10206207261596575f;

    for (int n = blockIdx.x * (blockDim.x >> 5) + warp; n < NN; n += nwarp) {
        const float4* m0 = (const float4*)(g_M0 + (size_t)n * 64);
        float o0 = 0.f;
        #pragma unroll
        for (int t = 0; t < 16; t++) {
            float4 v = m0[t];
            o0 += v.x * sW0T[(t * 4 + 0) * 32 + lane]
                + v.y * sW0T[(t * 4 + 1) * 32 + lane]
                + v.z * sW0T[(t * 4 + 2) * 32 + lane]
                + v.w * sW0T[(t * 4 + 3) * 32 + lane];
        }
        float o1x = 0.f, o1y = 0.f, o1z = 0.f;
        #pragma unroll
        for (int p = 0; p < 3; p++) {
            const float4* m1 = (const float4*)(g_M1 + (size_t)n * 288 + p * 96);
            #pragma unroll
            for (int q = 0; q < 8; q++) {
                float4 vx = m1[q];
                float4 vy = m1[8 + q];
                float4 vz = m1[16 + q];
                float wA = sW1T[(p * 32 + q * 4 + 0) * 32 + lane];
                float wB = sW1T[(p * 32 + q * 4 + 1) * 32 + lane];
                float wC = sW1T[(p * 32 + q * 4 + 2) * 32 + lane];
                float wD = sW1T[(p * 32 + q * 4 + 3) * 32 + lane];
                o1x += vx.x * wA + vx.y * wB + vx.z * wC + vx.w * wD;
                o1y += vy.x * wA + vy.y * wB + vy.z * wC + vy.w * wD;
                o1z += vz.x * wA + vz.y * wB + vz.z * wC + vz.w * wD;
            }
        }
        float4 r = make_float4(o0 * s64 * sA, o1x * s96 * sA, o1y * s96 * sA, o1z * s96 * sA);
        *(float4*)(out + (size_t)n * 128 + lane * 4) = r;
    }
}

// ---------------------------------------------------------------------------
extern "C" void kernel_launch(void* const* d_in, const int* in_sizes, int n_in,
                              void* d_out, int out_size)
{
    const float* na     = (const float*)d_in[0];
    const float* nf     = (const float*)d_in[1];
    const float* ea     = (const float*)d_in[2];
    const float* ef     = (const float*)d_in[3];
    const float* Wfirst = (const float*)d_in[4];
    const float* Wr0    = (const float*)d_in[5];
    const float* Wr1    = (const float*)d_in[6];
    const float* Wr2    = (const float*)d_in[7];
    const float* Wr3    = (const float*)d_in[8];
    const float* Ws0    = (const float*)d_in[9];
    const float* Ws1    = (const float*)d_in[10];
    const float* Wskip  = (const float*)d_in[11];
    const int*   idx_i  = (const int*)d_in[12];
    const int*   idx_j  = (const int*)d_in[13];
    float* out = (float*)d_out;

    cudaFuncSetAttribute(k_node, cudaFuncAttributeMaxDynamicSharedMemorySize, 22528 * 4);
    cudaFuncSetAttribute(k_edge, cudaFuncAttributeMaxDynamicSharedMemorySize, KE_SMEM_FLOATS * 4);

    void *pM0, *pM1;
    cudaGetSymbolAddress(&pM0, g_M0);
    cudaGetSymbolAddress(&pM1, g_M1);
    cudaMemsetAsync(pM0, 0, sizeof(float) * NN * 64, 0);
    cudaMemsetAsync(pM1, 0, sizeof(float) * NN * 288, 0);

    k_node<<<296, 512, 22528 * 4>>>(na, nf, Wskip, Wfirst, out + (size_t)NN * 128);
    k_edge<<<148, KE_THREADS, KE_SMEM_FLOATS * 4>>>(ef, ea, idx_i, idx_j, Wr0, Wr1, Wr2, Wr3);
    k_out<<<592, 128>>>(Ws0, Ws1, out);
}